// round 14
// baseline (speedup 1.0000x reference)
#include <cuda_runtime.h>
#include <cuda_bf16.h>
#include <cstdint>

// SumPooling / segment_sum with SORTED index (int32 or int64 — auto-detected).
// x: [N, 128] f32, index: [N] sorted, out: [16384, 128] f32.
//
// SINGLE persistent kernel (saves the K1 launch node + inter-kernel gap):
//   Phase 1: all CTAs cooperatively compute g_start[s] = lower_bound(index, s)
//            (4 elements/thread, vectorized loads).
//   Grid barrier (software, sense-reversing; all CTAs are resident by
//            construction: __launch_bounds__(256, 8) -> 32 regs -> 8 CTAs/SM,
//            grid = SMs*8, 64 warps/SM).
//   Phase 2: grid-strided CTA-per-segment streaming (proven R8/R10 body:
//            8 warps x float4/lane, 2-deep MLP, smem reduce, coalesced store).

#define D_FEAT      128
#define N_SEGMENTS  16384
#define THREADS     256
#define WARPS       8

__device__ int g_start[N_SEGMENTS + 1];
__device__ unsigned g_bar_count = 0;
__device__ unsigned g_bar_gen   = 0;

// JAX with x64 disabled silently downgrades int64 -> int32. Probe: read the
// middle of the buffer as int64. True int64 -> small value in [0,16384).
// int32 -> aliases two packed sorted int32s near the end -> huge.
__device__ __forceinline__ bool idx_is64(const void* __restrict__ idx, int n)
{
    long long probe = __ldg((const long long*)idx + ((n >> 1) - 1));
    return (probe >= 0 && probe < N_SEGMENTS);
}

// ---------------- Phase 1: boundaries (4 elements per thread) ----------------

template <bool IS64>
__device__ __forceinline__ void boundaries_phase(const void* __restrict__ index,
                                                 int n, int total_threads)
{
    for (int t = blockIdx.x * THREADS + threadIdx.x;
         (long long)t * 4 < n; t += total_threads)
    {
        const int base = t * 4;
        const int cnt  = (n - base >= 4) ? 4 : (n - base);

        int v[4];
        if (IS64) {
            const long long* p = (const long long*)index;
            if (cnt == 4) {
                longlong2 lo = __ldg((const longlong2*)(p + base));
                longlong2 hi = __ldg((const longlong2*)(p + base) + 1);
                v[0] = (int)lo.x; v[1] = (int)lo.y; v[2] = (int)hi.x; v[3] = (int)hi.y;
            } else {
                for (int k = 0; k < cnt; ++k) v[k] = (int)__ldg(p + base + k);
            }
        } else {
            const int* p = (const int*)index;
            if (cnt == 4) {
                int4 q = __ldg((const int4*)(p + base));
                v[0] = q.x; v[1] = q.y; v[2] = q.z; v[3] = q.w;
            } else {
                for (int k = 0; k < cnt; ++k) v[k] = __ldg(p + base + k);
            }
        }

        int prev;
        if (base == 0) prev = -1;
        else prev = IS64 ? (int)__ldg((const long long*)index + base - 1)
                         : __ldg((const int*)index + base - 1);

        #pragma unroll
        for (int k = 0; k < 4; ++k) {
            if (k < cnt) {
                // start[s] = base+k for all s in (prev, v[k]]
                for (int s = prev + 1; s <= v[k]; ++s) g_start[s] = base + k;
                prev = v[k];
            }
        }
        if (base + cnt == n) {
            for (int s = prev + 1; s <= N_SEGMENTS; ++s) g_start[s] = n;
        }
    }
}

// ---------------- Software grid barrier (all CTAs resident) -----------------

__device__ __forceinline__ void grid_barrier()
{
    __syncthreads();
    if (threadIdx.x == 0) {
        __threadfence();                                  // publish phase-1 writes
        const unsigned gen = atomicAdd(&g_bar_gen, 0u);   // read BEFORE arriving
        if (atomicAdd(&g_bar_count, 1u) == gridDim.x - 1u) {
            g_bar_count = 0;                              // reset for next replay
            __threadfence();
            atomicAdd(&g_bar_gen, 1u);                    // release
        } else {
            while (atomicAdd(&g_bar_gen, 0u) == gen) __nanosleep(64);
        }
        __threadfence();                                  // acquire
    }
    __syncthreads();
}

// ---------------- Fused kernel ----------------------------------------------

__global__ __launch_bounds__(THREADS, 8)
void fused_segsum_kernel(const float* __restrict__ x,
                         const void* __restrict__ index,
                         float* __restrict__ out, int n)
{
    const int total_threads = gridDim.x * THREADS;

    if (idx_is64(index, n)) boundaries_phase<true >(index, n, total_threads);
    else                    boundaries_phase<false>(index, n, total_threads);

    grid_barrier();

    // Phase 2: proven CTA-per-segment body, grid-strided over segments.
    __shared__ float4 red[WARPS][32];

    const int w    = threadIdx.x >> 5;
    const int lane = threadIdx.x & 31;
    const float4* __restrict__ x4 = reinterpret_cast<const float4*>(x);

    for (int seg = blockIdx.x; seg < N_SEGMENTS; seg += gridDim.x) {
        const int s0 = g_start[seg];
        const int s1 = g_start[seg + 1];

        float4 a0 = make_float4(0.f, 0.f, 0.f, 0.f);
        float4 a1 = make_float4(0.f, 0.f, 0.f, 0.f);

        int r = s0 + w;
        for (; r + WARPS < s1; r += 2 * WARPS) {
            float4 v0 = __ldg(x4 + (long long)r * 32 + lane);
            float4 v1 = __ldg(x4 + (long long)(r + WARPS) * 32 + lane);
            a0.x += v0.x; a0.y += v0.y; a0.z += v0.z; a0.w += v0.w;
            a1.x += v1.x; a1.y += v1.y; a1.z += v1.z; a1.w += v1.w;
        }
        if (r < s1) {
            float4 v0 = __ldg(x4 + (long long)r * 32 + lane);
            a0.x += v0.x; a0.y += v0.y; a0.z += v0.z; a0.w += v0.w;
        }
        a0.x += a1.x; a0.y += a1.y; a0.z += a1.z; a0.w += a1.w;

        red[w][lane] = a0;
        __syncthreads();

        if (threadIdx.x < 128) {
            const int t = threadIdx.x;
            float4 s = red[0][t & 31];
            #pragma unroll
            for (int ww = 1; ww < WARPS; ++ww) {
                float4 v = red[ww][t & 31];
                s.x += v.x; s.y += v.y; s.z += v.z; s.w += v.w;
            }
            float val = (t >> 5) == 0 ? s.x
                      : (t >> 5) == 1 ? s.y
                      : (t >> 5) == 2 ? s.z : s.w;
            out[(long long)seg * D_FEAT + 4 * (t & 31) + (t >> 5)] = val;
        }
        __syncthreads();   // protect red[] before next iteration
    }
}

extern "C" void kernel_launch(void* const* d_in, const int* in_sizes, int n_in,
                              void* d_out, int out_size)
{
    const float* x     = (const float*)d_in[0];
    const void*  index = d_in[1];
    float*       out   = (float*)d_out;

    const int n_rows = in_sizes[0] / D_FEAT;   // 1,000,000

    int dev = 0, sms = 148;
    cudaGetDevice(&dev);
    cudaDeviceGetAttribute(&sms, cudaDevAttrMultiProcessorCount, dev);

    // __launch_bounds__(256, 8) guarantees 8 CTAs/SM residency -> the grid
    // barrier is safe with grid = sms * 8 (all CTAs concurrently resident).
    const int grid = sms * 8;

    fused_segsum_kernel<<<grid, THREADS>>>(x, index, out, n_rows);
}

// round 15
// speedup vs baseline: 1.0774x; 1.0774x over previous
#include <cuda_runtime.h>
#include <cuda_bf16.h>
#include <cstdint>

// SumPooling / segment_sum with SORTED index (int32 or int64 — auto-detected).
// x: [N, 128] f32, index: [N] sorted, out: [16384, 128] f32.
//
// PROVEN-BEST two-kernel structure (R10 = 84.7us; fused/persistent variants
// regressed — HW-scheduled 16384-CTA grid load-balances variable-length
// segments better than persistent CTAs):
//   K1: vectorized pass over index (4 elements/thread) -> g_start[s] =
//       lower_bound(index, s). ~1.2us (8MB index read).
//   K2: one CTA per segment: 8 warps stream the segment's contiguous rows
//       (float4 per lane, 2-deep MLP), smem cross-warp reduce, coalesced
//       store. Runs at 82-83% DRAM = B300 achieved-bandwidth ceiling.
// Micro-lever this round: __ldcs (evict-first) on the once-read x stream so
// it doesn't occupy L2 ways needed by index/output lines.

#define D_FEAT      128
#define N_SEGMENTS  16384
#define K1_THREADS  256
#define WARPS       8

__device__ int g_start[N_SEGMENTS + 1];

// JAX with x64 disabled silently downgrades int64 -> int32. Probe: read the
// middle of the buffer as int64. True int64 -> small value in [0,16384).
// int32 -> aliases two packed sorted int32s near the end -> huge.
__device__ __forceinline__ bool idx_is64(const void* __restrict__ idx, int n)
{
    long long probe = __ldg((const long long*)idx + ((n >> 1) - 1));
    return (probe >= 0 && probe < N_SEGMENTS);
}

// ---------------- K1: boundaries (4 elements per thread) ----------------

template <bool IS64>
__device__ __forceinline__ void boundaries_body(const void* __restrict__ index, int n)
{
    const int t    = blockIdx.x * K1_THREADS + threadIdx.x;
    const int base = t * 4;
    if (base >= n) return;

    int v[4];
    const int cnt = (n - base >= 4) ? 4 : (n - base);

    if (IS64) {
        const long long* p = (const long long*)index;
        if (cnt == 4) {
            longlong2 lo = __ldg((const longlong2*)(p + base));
            longlong2 hi = __ldg((const longlong2*)(p + base) + 1);
            v[0] = (int)lo.x; v[1] = (int)lo.y; v[2] = (int)hi.x; v[3] = (int)hi.y;
        } else {
            for (int k = 0; k < cnt; ++k) v[k] = (int)__ldg(p + base + k);
        }
    } else {
        const int* p = (const int*)index;
        if (cnt == 4) {
            int4 q = __ldg((const int4*)(p + base));
            v[0] = q.x; v[1] = q.y; v[2] = q.z; v[3] = q.w;
        } else {
            for (int k = 0; k < cnt; ++k) v[k] = __ldg(p + base + k);
        }
    }

    int prev;
    if (base == 0) prev = -1;
    else prev = IS64 ? (int)__ldg((const long long*)index + base - 1)
                     : __ldg((const int*)index + base - 1);

    #pragma unroll
    for (int k = 0; k < 4; ++k) {
        if (k < cnt) {
            // start[s] = base+k for all s in (prev, v[k]]
            for (int s = prev + 1; s <= v[k]; ++s) g_start[s] = base + k;
            prev = v[k];
        }
    }

    if (base + cnt == n) {
        for (int s = prev + 1; s <= N_SEGMENTS; ++s) g_start[s] = n;
    }
}

__global__ __launch_bounds__(K1_THREADS)
void seg_boundaries_kernel(const void* __restrict__ index, int n)
{
    if (idx_is64(index, n)) boundaries_body<true >(index, n);
    else                    boundaries_body<false>(index, n);
}

// ---------------- K2: CTA per segment (proven design + streaming loads) -----

__device__ __forceinline__ float4 ldcs4(const float4* p)
{
#if __CUDA_ARCH__ >= 320
    return __ldcs(p);     // evict-first: x is read exactly once
#else
    return __ldg(p);
#endif
}

__global__ __launch_bounds__(WARPS * 32)
void segsum_kernel(const float* __restrict__ x, float* __restrict__ out)
{
    __shared__ float4 red[WARPS][32];

    const int seg  = blockIdx.x;
    const int w    = threadIdx.x >> 5;
    const int lane = threadIdx.x & 31;

    const int s0 = g_start[seg];
    const int s1 = g_start[seg + 1];

    const float4* __restrict__ x4 = reinterpret_cast<const float4*>(x);

    float4 a0 = make_float4(0.f, 0.f, 0.f, 0.f);
    float4 a1 = make_float4(0.f, 0.f, 0.f, 0.f);

    int r = s0 + w;
    for (; r + WARPS < s1; r += 2 * WARPS) {
        float4 v0 = ldcs4(x4 + (long long)r * 32 + lane);
        float4 v1 = ldcs4(x4 + (long long)(r + WARPS) * 32 + lane);
        a0.x += v0.x; a0.y += v0.y; a0.z += v0.z; a0.w += v0.w;
        a1.x += v1.x; a1.y += v1.y; a1.z += v1.z; a1.w += v1.w;
    }
    if (r < s1) {
        float4 v0 = ldcs4(x4 + (long long)r * 32 + lane);
        a0.x += v0.x; a0.y += v0.y; a0.z += v0.z; a0.w += v0.w;
    }
    a0.x += a1.x; a0.y += a1.y; a0.z += a1.z; a0.w += a1.w;

    red[w][lane] = a0;
    __syncthreads();

    if (threadIdx.x < 128) {
        const int t = threadIdx.x;
        float4 s = red[0][t & 31];
        #pragma unroll
        for (int ww = 1; ww < WARPS; ++ww) {
            float4 v = red[ww][t & 31];
            s.x += v.x; s.y += v.y; s.z += v.z; s.w += v.w;
        }
        float val = (t >> 5) == 0 ? s.x
                  : (t >> 5) == 1 ? s.y
                  : (t >> 5) == 2 ? s.z : s.w;
        out[(long long)seg * D_FEAT + 4 * (t & 31) + (t >> 5)] = val;
    }
}

extern "C" void kernel_launch(void* const* d_in, const int* in_sizes, int n_in,
                              void* d_out, int out_size)
{
    const float* x     = (const float*)d_in[0];
    const void*  index = d_in[1];
    float*       out   = (float*)d_out;

    const int n_rows = in_sizes[0] / D_FEAT;   // 1,000,000

    const int k1_threads_total = (n_rows + 3) / 4;
    seg_boundaries_kernel<<<(k1_threads_total + K1_THREADS - 1) / K1_THREADS,
                            K1_THREADS>>>(index, n_rows);
    segsum_kernel<<<N_SEGMENTS, WARPS * 32>>>(x, out);
}